// round 17
// baseline (speedup 1.0000x reference)
#include <cuda_runtime.h>
#include <cstdint>

#define BUF_ROWS 65536
#define ROW_DIM  1024
#define NT       256
#define WPB      8                 // warps per block
#define NBLOCKS  296               // 148 SMs * 2 RESIDENT blocks (= grid; no dead wave)
#define GRAB     4                 // rows per steal (BUF_ROWS % GRAB == 0)

// Output layout (fp32, flattened reference tuple):
//   [0, 67108864)          buf
//   67108864               buffer_occupancy
//   67108865               average_age
//   [67108866, 67174402)   candidates (0/1)   <-- base byte addr % 16 == 8 !
//   67174402               consolidation_pressure
//   [67174403, ...)        ltm_ready  (base % 4 == 3 -> base+1 is 16B-aligned)
#define OFF_OCC   ((size_t)67108864)
#define OFF_AGE   ((size_t)67108865)
#define OFF_CAND  ((size_t)67108866)
#define OFF_PRESS ((size_t)67174402)
#define OFF_LTM   ((size_t)67174403)

__device__ float g_age[NBLOCKS];
__device__ int   g_occ[NBLOCKS];
__device__ int   g_press[NBLOCKS];
__device__ int   g_count = 0;   // blocks-done counter
__device__ int   g_next  = 0;   // work-steal row cursor (reset by last block)

// ---------------------------------------------------------------------------
// Persistent kernel, warp-per-row, work-stealing, ROW-PIPELINED:
// next row's 8 LDG.128 are issued BEFORE the current row's 16 STG.128, so the
// read stream never drains while stores retire (double-buffered registers).
// Grid == resident blocks: every block participates from t=0; the finalizer
// runs the moment the last worker finishes (no trailing launch wave).
// ---------------------------------------------------------------------------
__global__ void __launch_bounds__(NT, 2) k_main(
    const float* __restrict__ new_input,
    const float* __restrict__ mem,
    const float* __restrict__ ages,
    const float* __restrict__ tags,
    const float* __restrict__ strs,
    const int*   __restrict__ wpos,
    const float* __restrict__ evp,
    const float* __restrict__ dtp,
    float*       __restrict__ out)
{
    const int t    = threadIdx.x;
    const int warp = t >> 5;
    const int lane = t & 31;

    int pos = wpos[0] % BUF_ROWS;
    if (pos < 0) pos += BUF_ROWS;
    const float ev = evp[0];
    const float dt = dtp[0];

    float age_acc = 0.0f;
    int   occ_acc = 0, press_acc = 0;

    // ---- steal first grab, prefetch its first row ----
    int base = 0;
    if (lane == 0) base = atomicAdd(&g_next, GRAB);
    base = __shfl_sync(0xffffffffu, base, 0);

    float4 v[2][8];   // double-buffered row registers
    if (base < BUF_ROWS) {
        const float4* s0 = reinterpret_cast<const float4*>(
            (base == pos) ? new_input : (mem + (size_t)base * ROW_DIM));
        #pragma unroll
        for (int c = 0; c < 8; c++) v[0][c] = __ldcs(s0 + c * 32 + lane);
    }

    while (base < BUF_ROWS) {
        // per-grab scalar vectors (base % 4 == 0 -> aligned float4)
        const float4 a4 = *reinterpret_cast<const float4*>(ages + base);
        const float4 t4 = *reinterpret_cast<const float4*>(tags + base);
        const float4 s4 = *reinterpret_cast<const float4*>(strs + base);

        float4 cand4;
        int nbase = BUF_ROWS;

        #pragma unroll
        for (int j = 0; j < GRAB; j++) {
            // ---- prefetch the NEXT row before storing the current one ----
            if (j < GRAB - 1) {
                const int rn = base + j + 1;
                const float4* sn = reinterpret_cast<const float4*>(
                    (rn == pos) ? new_input : (mem + (size_t)rn * ROW_DIM));
                #pragma unroll
                for (int c = 0; c < 8; c++)
                    v[(j + 1) & 1][c] = __ldcs(sn + c * 32 + lane);
            } else {
                if (lane == 0) nbase = atomicAdd(&g_next, GRAB);
                nbase = __shfl_sync(0xffffffffu, nbase, 0);
                if (nbase < BUF_ROWS) {
                    const float4* sn = reinterpret_cast<const float4*>(
                        (nbase == pos) ? new_input : (mem + (size_t)nbase * ROW_DIM));
                    #pragma unroll
                    for (int c = 0; c < 8; c++)
                        v[(j + 1) & 1][c] = __ldcs(sn + c * 32 + lane);
                }
            }

            // ---- process current row (buffer parity j&1) ----
            const int   r      = base + j;
            const bool  is_pos = (r == pos);
            const float age_in = (j == 0) ? a4.x : (j == 1) ? a4.y : (j == 2) ? a4.z : a4.w;
            const float tag_in = (j == 0) ? t4.x : (j == 1) ? t4.y : (j == 2) ? t4.z : t4.w;
            const float str_in = (j == 0) ? s4.x : (j == 1) ? s4.y : (j == 2) ? s4.z : s4.w;

            const float age      = is_pos ? 0.0f : (age_in + dt);
            const float tag      = is_pos ? ev   : tag_in;
            const float strength = is_pos ? 0.0f : str_in;   // pos row never a candidate

            float af = fminf(fmaxf(1.0f - age * 1e-4f, 0.1f), 1.0f);
            const float decay = 0.95f * af * (1.0f + 0.3f * fabsf(tag));

            float4* cur = v[j & 1];
            float p = 0.0f;
            #pragma unroll
            for (int c = 0; c < 8; c++) {
                cur[c].x *= decay; cur[c].y *= decay;
                cur[c].z *= decay; cur[c].w *= decay;
                p += fabsf(cur[c].x) + fabsf(cur[c].y)
                   + fabsf(cur[c].z) + fabsf(cur[c].w);
            }

            // buf store: aligned float4, streaming
            float4* bdst = reinterpret_cast<float4*>(out + (size_t)r * ROW_DIM);
            #pragma unroll
            for (int c = 0; c < 8; c++) __stcs(bdst + c * 32 + lane, cur[c]);

            // warp-reduce row abs-sum
            #pragma unroll
            for (int o = 16; o > 0; o >>= 1) p += __shfl_xor_sync(0xffffffffu, p, o);

            const bool cand = (strength > 0.5f) && (age > 100.0f) && (p > 0.1f);
            const float cf = cand ? 1.0f : 0.0f;
            if (j == 0) cand4.x = cf; else if (j == 1) cand4.y = cf;
            else if (j == 2) cand4.z = cf; else cand4.w = cf;

            // ltm: base % 4 == 3 -> aligned float4 stores at +1 with shift-by-one
            float* ltm = out + OFF_LTM + (size_t)r * ROW_DIM;
            const float4 zero = make_float4(0.f, 0.f, 0.f, 0.f);
            #pragma unroll
            for (int c = 0; c < 8; c++) {
                float xn      = (c < 7) ? cur[c + 1].x : 0.0f;
                float nx_same = __shfl_down_sync(0xffffffffu, cur[c].x, 1);
                float nx_next = __shfl_sync(0xffffffffu, xn, 0);
                float nx      = (lane == 31) ? nx_next : nx_same;
                float4 w = cand ? make_float4(cur[c].y, cur[c].z, cur[c].w, nx) : zero;
                if (c < 7 || lane < 31)
                    __stcs(reinterpret_cast<float4*>(ltm + 1) + c * 32 + lane, w);
            }
            if (lane == 31) {   // row tail: elements 1021..1023
                ltm[ROW_DIM - 3] = cand ? cur[7].y : 0.0f;
                ltm[ROW_DIM - 2] = cand ? cur[7].z : 0.0f;
                ltm[ROW_DIM - 1] = cand ? cur[7].w : 0.0f;
            }
            if (lane == 0) {
                ltm[0] = cand ? cur[0].x : 0.0f;
                age_acc   += age;
                occ_acc   += (p > 0.01f) ? 1 : 0;
                press_acc += cand ? 1 : 0;
            }
        }

        // batched candidate flags: OFF_CAND byte addr % 16 == 8, so the widest
        // legal vector here is float2 (8B-aligned). Two STG.64 per grab.
        if (lane == 0) {
            float* cdst = out + OFF_CAND + (size_t)base;
            __stcs(reinterpret_cast<float2*>(cdst),     make_float2(cand4.x, cand4.y));
            __stcs(reinterpret_cast<float2*>(cdst + 2), make_float2(cand4.z, cand4.w));
        }

        base = nbase;   // next grab's row 0 is already in flight in v[0]
    }

    // ---- block-level reduction of per-warp accumulators ----
    __shared__ float sa[WPB];
    __shared__ int   so[WPB], sc[WPB];
    __shared__ int   s_last;
    if (lane == 0) { sa[warp] = age_acc; so[warp] = occ_acc; sc[warp] = press_acc; }
    __syncthreads();
    if (t == 0) {
        float a = 0.0f; int o = 0, c = 0;
        #pragma unroll
        for (int i = 0; i < WPB; i++) { a += sa[i]; o += so[i]; c += sc[i]; }
        g_age[blockIdx.x]   = a;
        g_occ[blockIdx.x]   = o;
        g_press[blockIdx.x] = c;
        __threadfence();
        s_last = (atomicAdd(&g_count, 1) == NBLOCKS - 1) ? 1 : 0;
    }
    __syncthreads();

    // ---- last block finalizes the 3 scalars and resets counters ----
    if (s_last) {
        float a = 0.0f; int o = 0, c = 0;
        for (int i = t; i < NBLOCKS; i += NT) {
            a += __ldcg(&g_age[i]);
            o += __ldcg(&g_occ[i]);
            c += __ldcg(&g_press[i]);
        }
        #pragma unroll
        for (int s = 16; s > 0; s >>= 1) {
            a += __shfl_xor_sync(0xffffffffu, a, s);
            o += __shfl_xor_sync(0xffffffffu, o, s);
            c += __shfl_xor_sync(0xffffffffu, c, s);
        }
        __shared__ float fa[WPB];
        __shared__ int   fo[WPB], fc[WPB];
        if (lane == 0) { fa[warp] = a; fo[warp] = o; fc[warp] = c; }
        __syncthreads();
        if (t == 0) {
            float ta = 0.0f; int to = 0, tc = 0;
            #pragma unroll
            for (int i = 0; i < WPB; i++) { ta += fa[i]; to += fo[i]; tc += fc[i]; }
            out[OFF_OCC]   = (float)to * (1.0f / (float)BUF_ROWS);
            out[OFF_AGE]   = ta        * (1.0f / (float)BUF_ROWS);
            out[OFF_PRESS] = (float)tc;
            g_count = 0;   // reset for next graph replay
            g_next  = 0;
        }
    }
}

// ---------------------------------------------------------------------------
extern "C" void kernel_launch(void* const* d_in, const int* in_sizes, int n_in,
                              void* d_out, int out_size) {
    const float* new_input = (const float*)d_in[0];
    const float* mem       = (const float*)d_in[1];
    const float* ages      = (const float*)d_in[2];
    const float* tags      = (const float*)d_in[3];
    const float* strs      = (const float*)d_in[4];
    const int*   wpos      = (const int*)  d_in[5];
    const float* evp       = (const float*)d_in[6];
    const float* dtp       = (const float*)d_in[7];
    float*       out       = (float*)d_out;

    k_main<<<NBLOCKS, NT>>>(new_input, mem, ages, tags, strs, wpos, evp, dtp, out);
}